// round 8
// baseline (speedup 1.0000x reference)
#include <cuda_runtime.h>
#include <cuda_fp16.h>
#include <cstdint>

// ---------------------------------------------------------------------------
// TFN forward. R8: main kernel warp-specialized. 384 thr = 8 consumer warps
// (4m x 2n fp16 mma grid, as R7) + 4 producer warps (LDG->cvt->STS staging).
// 3-stage smem ring with full/empty mbarriers; no __syncthreads in mainloop.
// Removes the per-chunk full-CTA barrier convoy that held R7 at ~2150
// cyc/chunk vs the ~1600 cyc DRAM pacing floor.
// ---------------------------------------------------------------------------

#define NBLK   152
#define BDIM   64
#define HDIM   96
#define LDH    104            // smem B row stride in halfs (208 B, LDSM conflict-free)
#define KROWS  112            // 97 data rows + 15 zero pad (7 k16 steps)
#define WBUFH  (KROWS * LDH)  // halfs per stage buffer
#define STAGES 3
#define SMEM_BYTES (STAGES*WBUFH*2 + 2*6208*4)

__device__ float g_a1[BDIM * 97];
__device__ float g_v1[BDIM * 97];
__device__ float g_t1[BDIM * 97];
__device__ float g_part[NBLK * BDIM * HDIM];

// ---------------------------------------------------------------------------

__device__ __forceinline__ uint32_t s2u(const void* p) {
    uint32_t a;
    asm("{ .reg .u64 t; cvta.to.shared.u64 t, %1; cvt.u32.u64 %0, t; }"
        : "=r"(a) : "l"(p));
    return a;
}

__device__ __forceinline__ void mbar_init(uint32_t addr, uint32_t cnt) {
    asm volatile("mbarrier.init.shared.b64 [%0], %1;" :: "r"(addr), "r"(cnt)
                 : "memory");
}
__device__ __forceinline__ void mbar_arrive(uint32_t addr) {
    asm volatile("mbarrier.arrive.shared.b64 _, [%0];" :: "r"(addr) : "memory");
}
__device__ __forceinline__ void mbar_wait(uint32_t addr, uint32_t parity) {
    uint32_t done;
    asm volatile(
        "{\n\t"
        ".reg .pred p;\n\t"
        "mbarrier.try_wait.parity.acquire.cta.shared::cta.b64 p, [%1], %2;\n\t"
        "selp.b32 %0, 1, 0, p;\n\t"
        "}"
        : "=r"(done) : "r"(addr), "r"(parity) : "memory");
    if (!done) {
        asm volatile(
            "{\n\t"
            ".reg .pred P1;\n\t"
            "WAIT_LOOP_%=:\n\t"
            "mbarrier.try_wait.parity.acquire.cta.shared::cta.b64 P1, [%0], %1, 0x989680;\n\t"
            "@P1 bra.uni WAIT_DONE_%=;\n\t"
            "bra.uni WAIT_LOOP_%=;\n\t"
            "WAIT_DONE_%=:\n\t"
            "}"
            :: "r"(addr), "r"(parity) : "memory");
    }
}

__device__ __forceinline__ uint32_t h2u(__half2 h) {
    return *reinterpret_cast<uint32_t*>(&h);
}

__device__ __forceinline__ void mma_f16(float c[4],
                                        uint32_t a0, uint32_t a1,
                                        uint32_t a2, uint32_t a3,
                                        uint32_t b0, uint32_t b1) {
    asm volatile(
        "mma.sync.aligned.m16n8k16.row.col.f32.f16.f16.f32 "
        "{%0,%1,%2,%3}, {%4,%5,%6,%7}, {%8,%9}, {%0,%1,%2,%3};"
        : "+f"(c[0]), "+f"(c[1]), "+f"(c[2]), "+f"(c[3])
        : "r"(a0), "r"(a1), "r"(a2), "r"(a3), "r"(b0), "r"(b1));
}

struct __align__(8) H4 { __half2 a, b; };

__device__ __forceinline__ void cvt_store(__half* buf, int q, float4 v) {
    int e = q * 4;
    int t = e / 96;
    int c = e - t * 96;
    H4 o;
    o.a = __floats2half2_rn(v.x, v.y);
    o.b = __floats2half2_rn(v.z, v.w);
    *reinterpret_cast<H4*>(buf + t * LDH + c) = o;
}

// ---------------------------------------------------------------------------
// Kernel 1: encoders. grid (64 batch, 3 mods), 768 threads = 96 h x 8 slices.
// ---------------------------------------------------------------------------
__global__ void __launch_bounds__(768) tfn_enc(
    const float* __restrict__ audios, const float* __restrict__ texts,
    const float* __restrict__ videos,
    const float* __restrict__ Wa, const float* __restrict__ ba,
    const float* __restrict__ Wt, const float* __restrict__ bt,
    const float* __restrict__ Wv, const float* __restrict__ bv) {
    const int b   = blockIdx.x;
    const int mod = blockIdx.y;
    const int tid = threadIdx.x;

    const float* x; const float* W; const float* bias; float* out; int K;
    if (mod == 0)      { x = audios; W = Wa; bias = ba; out = g_a1; K = 512; }
    else if (mod == 1) { x = texts;  W = Wt; bias = bt; out = g_t1; K = 1024; }
    else               { x = videos; W = Wv; bias = bv; out = g_v1; K = 512; }

    __shared__ float xs[1024];
    __shared__ float ps[768];

    const float* xb = x + (size_t)b * K;
    for (int i = tid; i < K; i += 768) xs[i] = xb[i];
    __syncthreads();

    const int h  = tid % 96;
    const int g  = tid / 96;           // 0..7
    const int kq = K >> 3;             // 64 or 128
    const int k0 = g * kq;

    float acc = 0.f;
#pragma unroll 8
    for (int k = k0; k < k0 + kq; k++)
        acc += xs[k] * W[k * HDIM + h];
    ps[tid] = acc;
    __syncthreads();

    if (g == 0) {
        float r = bias[h];
#pragma unroll
        for (int i = 0; i < 8; i++) r += ps[h + 96 * i];
        out[b * 97 + 1 + h] = fmaxf(r, 0.f);
        if (h == 0) out[b * 97] = 1.f;
    }
}

// ---------------------------------------------------------------------------
// Kernel 2: main fused trilinear GEMM, warp-specialized.
//   152 CTAs x 384 thr: warps 0-7 consumers (mma), warps 8-11 producers.
// ---------------------------------------------------------------------------
__global__ void __launch_bounds__(384, 1) tfn_main(const float* __restrict__ W1) {
    extern __shared__ char smx[];
    __half* wring = reinterpret_cast<__half*>(smx);
    float*  a1s   = reinterpret_cast<float*>(smx + STAGES * WBUFH * 2);
    float*  v1s   = a1s + 6208;

    __shared__ __align__(8) uint64_t mbars[2 * STAGES];  // full[0..2], empty[0..2]
    const uint32_t fullb  = s2u(&mbars[0]);
    const uint32_t emptyb = s2u(&mbars[STAGES]);

    const int tid  = threadIdx.x;
    const int lane = tid & 31;
    const int wid  = tid >> 5;

    const int bk = blockIdx.x;
    // 9409 = 152*61 + 137 : first 137 blocks take 62 chunks
    const int cstart = (bk < 137) ? bk * 62 : bk * 61 + 137;
    const int ccnt   = (bk < 137) ? 62 : 61;

    // ---- init: barriers, tables, zero-pad ring k-tail rows ----
    if (tid == 0) {
#pragma unroll
        for (int s = 0; s < STAGES; s++) {
            mbar_init(fullb + 8 * s, 128);    // 4 producer warps x 32
            mbar_init(emptyb + 8 * s, 256);   // 8 consumer warps x 32
        }
    }
    for (int i = tid; i < 6208; i += 384) { a1s[i] = g_a1[i]; v1s[i] = g_v1[i]; }
    {
        // rows 97..111 of each stage = 15*LDH halfs = 780 u32 per stage
        for (int i = tid; i < STAGES * 780; i += 384) {
            int s = i / 780, r = i - s * 780;
            reinterpret_cast<uint32_t*>(wring + s * WBUFH + 97 * LDH)[r] = 0;
        }
    }
    __syncthreads();

    if (wid < 8) {
        // ================= CONSUMERS =================
        const int wm    = wid & 3;          // batch rows 16*wm..16*wm+15
        const int wn    = wid >> 2;         // cols 48*wn..48*wn+47
        const int gid   = lane >> 2;
        const int tig   = lane & 3;
        const int b0    = wm * 16 + gid;
        const int nbase = wn * 48;
        const int lrow  = lane & 15;
        const int lcol  = (lane >> 4) * 8;

        __half2 t1f[7][4];
#pragma unroll
        for (int ks = 0; ks < 7; ks++) {
            int ka = ks * 16 + 2 * tig;
            int kb = ka + 8;
            float x0 = (ka     < 97) ? g_t1[b0 * 97 + ka]           : 0.f;
            float x1 = (ka + 1 < 97) ? g_t1[b0 * 97 + ka + 1]       : 0.f;
            float y0 = (ka     < 97) ? g_t1[(b0 + 8) * 97 + ka]     : 0.f;
            float y1 = (ka + 1 < 97) ? g_t1[(b0 + 8) * 97 + ka + 1] : 0.f;
            float x2 = (kb     < 97) ? g_t1[b0 * 97 + kb]           : 0.f;
            float x3 = (kb + 1 < 97) ? g_t1[b0 * 97 + kb + 1]       : 0.f;
            float y2 = (kb     < 97) ? g_t1[(b0 + 8) * 97 + kb]     : 0.f;
            float y3 = (kb + 1 < 97) ? g_t1[(b0 + 8) * 97 + kb + 1] : 0.f;
            t1f[ks][0] = __floats2half2_rn(x0, x1);
            t1f[ks][1] = __floats2half2_rn(y0, y1);
            t1f[ks][2] = __floats2half2_rn(x2, x3);
            t1f[ks][3] = __floats2half2_rn(y2, y3);
        }

        float Y[6][4];
#pragma unroll
        for (int j = 0; j < 6; j++) { Y[j][0] = Y[j][1] = Y[j][2] = Y[j][3] = 0.f; }

        int st = 0, ph = 0;
        for (int ci = 0; ci < ccnt; ci++) {
            mbar_wait(fullb + 8 * st, ph);
            const __half* cur = wring + st * WBUFH;

            const int av = cstart + ci;
            const int ca = av / 97;
            const int cv = av - ca * 97;
            const __half2 m0h = __float2half2_rn(a1s[b0 * 97 + ca] * v1s[b0 * 97 + cv]);
            const __half2 m1h = __float2half2_rn(a1s[(b0 + 8) * 97 + ca] * v1s[(b0 + 8) * 97 + cv]);

#pragma unroll
            for (int ks = 0; ks < 7; ks++) {
                const uint32_t A0 = h2u(__hmul2(m0h, t1f[ks][0]));
                const uint32_t A1 = h2u(__hmul2(m1h, t1f[ks][1]));
                const uint32_t A2 = h2u(__hmul2(m0h, t1f[ks][2]));
                const uint32_t A3 = h2u(__hmul2(m1h, t1f[ks][3]));
                const __half* rowp = cur + (ks * 16 + lrow) * LDH + nbase + lcol;
#pragma unroll
                for (int j3 = 0; j3 < 3; j3++) {
                    uint32_t saddr =
                        (uint32_t)__cvta_generic_to_shared(rowp + 16 * j3);
                    uint32_t B0, B1, B2, B3;
                    asm volatile(
                        "ldmatrix.sync.aligned.m8n8.x4.trans.shared.b16 "
                        "{%0,%1,%2,%3}, [%4];"
                        : "=r"(B0), "=r"(B1), "=r"(B2), "=r"(B3) : "r"(saddr));
                    mma_f16(Y[2 * j3],     A0, A1, A2, A3, B0, B1);
                    mma_f16(Y[2 * j3 + 1], A0, A1, A2, A3, B2, B3);
                }
            }

            mbar_arrive(emptyb + 8 * st);
            if (++st == STAGES) { st = 0; ph ^= 1; }
        }

        // write fp32 partials [bk][b][h]
        float* dst = g_part + (size_t)bk * (BDIM * HDIM);
#pragma unroll
        for (int j = 0; j < 6; j++) {
            int h = nbase + 8 * j + 2 * tig;
            *reinterpret_cast<float2*>(dst + b0 * HDIM + h) =
                make_float2(Y[j][0], Y[j][1]);
            *reinterpret_cast<float2*>(dst + (b0 + 8) * HDIM + h) =
                make_float2(Y[j][2], Y[j][3]);
        }
    } else {
        // ================= PRODUCERS (warps 8-11, 128 threads) =================
        const int ptid = tid - 256;   // 0..127
        int st = 0, ph = 1;           // first empty-wait passes immediately

        for (int ci = 0; ci < ccnt; ci++) {
            // issue LDGs for this chunk BEFORE the backpressure wait
            const float4* src = reinterpret_cast<const float4*>(
                W1 + (size_t)(cstart + ci) * 9312);
            float4 stg[19];
#pragma unroll
            for (int j = 0; j < 18; j++) stg[j] = src[ptid + j * 128];
            if (ptid < 24) stg[18] = src[2304 + ptid];

            mbar_wait(emptyb + 8 * st, ph);
            __half* buf = wring + st * WBUFH;
#pragma unroll
            for (int j = 0; j < 18; j++) cvt_store(buf, ptid + j * 128, stg[j]);
            if (ptid < 24) cvt_store(buf, 2304 + ptid, stg[18]);

            mbar_arrive(fullb + 8 * st);
            if (++st == STAGES) { st = 0; ph ^= 1; }
        }
    }
}

// ---------------------------------------------------------------------------
// Kernel 3: reduce partials + bias/relu + W2 + heads. One block per batch row.
// ---------------------------------------------------------------------------
__global__ void __launch_bounds__(768) tfn_tail(
    const float* __restrict__ b1, const float* __restrict__ W2,
    const float* __restrict__ b2,
    const float* __restrict__ Wo1, const float* __restrict__ bo1,
    const float* __restrict__ Wo2, const float* __restrict__ bo2,
    const float* __restrict__ Wo3, const float* __restrict__ bo3,
    float* __restrict__ out) {
    __shared__ float ps[768];
    __shared__ float yr[HDIM];
    __shared__ float fs[HDIM];
    const int b   = blockIdx.x;
    const int tid = threadIdx.x;
    const int h   = tid % 96;
    const int g   = tid / 96;   // 0..7

    float acc = 0.f;
#pragma unroll 4
    for (int p = g; p < NBLK; p += 8)
        acc += g_part[(size_t)p * (BDIM * HDIM) + b * HDIM + h];
    ps[tid] = acc;
    __syncthreads();

    if (g == 0) {
        float r = b1[h];
#pragma unroll
        for (int i = 0; i < 8; i++) r += ps[h + 96 * i];
        yr[h] = fmaxf(r, 0.f);
    }
    __syncthreads();

    if (g == 0) {
        float f = b2[h];
#pragma unroll 8
        for (int k = 0; k < HDIM; k++) f += yr[k] * W2[k * HDIM + h];
        f = fmaxf(f, 0.f);
        fs[h] = f;
        out[b * HDIM + h] = f;
    }
    __syncthreads();

    if (tid < 6) {
        float a = bo1[tid];
        for (int k = 0; k < HDIM; k++) a += fs[k] * Wo1[k * 6 + tid];
        out[6144 + b * 6 + tid] = a;
    } else if (tid == 6) {
        float a = bo2[0];
        for (int k = 0; k < HDIM; k++) a += fs[k] * Wo2[k];
        out[6528 + b] = a;
    } else if (tid < 10) {
        int o = tid - 7;
        float a = bo3[o];
        for (int k = 0; k < HDIM; k++) a += fs[k] * Wo3[k * 3 + o];
        out[6592 + b * 3 + o] = a;
    }
    if (b == 0 && tid == 95) out[6784] = 0.f;  // interloss
}

// ---------------------------------------------------------------------------

extern "C" void kernel_launch(void* const* d_in, const int* in_sizes, int n_in,
                              void* d_out, int out_size) {
    (void)in_sizes; (void)n_in; (void)out_size;
    const float* audios = (const float*)d_in[0];
    const float* texts  = (const float*)d_in[1];
    const float* videos = (const float*)d_in[2];
    const float* Wa  = (const float*)d_in[3];
    const float* ba  = (const float*)d_in[4];
    const float* Wt  = (const float*)d_in[5];
    const float* bt  = (const float*)d_in[6];
    const float* Wv  = (const float*)d_in[7];
    const float* bv  = (const float*)d_in[8];
    const float* W1  = (const float*)d_in[9];
    const float* b1  = (const float*)d_in[10];
    const float* W2  = (const float*)d_in[11];
    const float* b2  = (const float*)d_in[12];
    const float* Wo1 = (const float*)d_in[13];
    const float* bo1 = (const float*)d_in[14];
    const float* Wo2 = (const float*)d_in[15];
    const float* bo2 = (const float*)d_in[16];
    const float* Wo3 = (const float*)d_in[17];
    const float* bo3 = (const float*)d_in[18];
    float* out = (float*)d_out;

    cudaFuncSetAttribute(tfn_main, cudaFuncAttributeMaxDynamicSharedMemorySize,
                         SMEM_BYTES);

    tfn_enc<<<dim3(64, 3), 768>>>(audios, texts, videos, Wa, ba, Wt, bt, Wv, bv);
    tfn_main<<<NBLK, 384, SMEM_BYTES>>>(W1);
    tfn_tail<<<64, 768>>>(b1, W2, b2, Wo1, bo1, Wo2, bo2, Wo3, bo3, out);
}

// round 9
// speedup vs baseline: 1.0986x; 1.0986x over previous
#include <cuda_runtime.h>
#include <cuda_fp16.h>
#include <cstdint>

// ---------------------------------------------------------------------------
// TFN forward. R9: revert R8's warp specialization (mbarrier waits + fewer
// consumer warps regressed). Back to R7 structure with TRUE prefetch
// distance 3: 3-stage smem ring (register-rotated pointers), 2 static reg
// staging sets. Chunk j's LDG issues at iter j-3... consumed by STS at iter
// j-1 => 2 full periods of latency cover (R7 only had 1, exposing ~1000 cyc
// of LDG tail per chunk).
// ---------------------------------------------------------------------------

#define NBLK   152
#define BDIM   64
#define HDIM   96
#define LDH    104            // smem B row stride in halfs (208 B, LDSM conflict-free)
#define KROWS  112            // 97 data rows + 15 zero pad (7 k16 steps)
#define WBUFH  (KROWS * LDH)  // halfs per stage buffer
#define SMEM_BYTES (3*WBUFH*2 + 2*6208*4)

__device__ float g_a1[BDIM * 97];
__device__ float g_v1[BDIM * 97];
__device__ float g_t1[BDIM * 97];
__device__ float g_part[NBLK * BDIM * HDIM];

// ---------------------------------------------------------------------------

__device__ __forceinline__ uint32_t h2u(__half2 h) {
    return *reinterpret_cast<uint32_t*>(&h);
}

__device__ __forceinline__ void mma_f16(float c[4],
                                        uint32_t a0, uint32_t a1,
                                        uint32_t a2, uint32_t a3,
                                        uint32_t b0, uint32_t b1) {
    asm volatile(
        "mma.sync.aligned.m16n8k16.row.col.f32.f16.f16.f32 "
        "{%0,%1,%2,%3}, {%4,%5,%6,%7}, {%8,%9}, {%0,%1,%2,%3};"
        : "+f"(c[0]), "+f"(c[1]), "+f"(c[2]), "+f"(c[3])
        : "r"(a0), "r"(a1), "r"(a2), "r"(a3), "r"(b0), "r"(b1));
}

struct __align__(8) H4 { __half2 a, b; };

// 97*96 = 9312 floats = 2328 float4 per chunk. 256 threads: 9 each + 24 extra.
__device__ __forceinline__ void stage_ldg(float4 (&stg)[10],
                                          const float* __restrict__ W1,
                                          int av, int tid) {
    const float4* src = reinterpret_cast<const float4*>(W1 + (size_t)av * 9312);
#pragma unroll
    for (int j = 0; j < 9; j++) stg[j] = src[tid + j * 256];
    if (tid < 24) stg[9] = src[2304 + tid];
}

__device__ __forceinline__ void cvt_store(__half* buf, int q, float4 v) {
    int e = q * 4;
    int t = e / 96;
    int c = e - t * 96;
    H4 o;
    o.a = __floats2half2_rn(v.x, v.y);
    o.b = __floats2half2_rn(v.z, v.w);
    *reinterpret_cast<H4*>(buf + t * LDH + c) = o;
}

__device__ __forceinline__ void stage_sts(__half* buf, const float4 (&stg)[10],
                                          int tid) {
#pragma unroll
    for (int j = 0; j < 9; j++) cvt_store(buf, tid + j * 256, stg[j]);
    if (tid < 24) cvt_store(buf, 2304 + tid, stg[9]);
}

// ---------------------------------------------------------------------------
// Kernel 1: encoders. grid (64 batch, 3 mods), 768 threads = 96 h x 8 slices.
// ---------------------------------------------------------------------------
__global__ void __launch_bounds__(768) tfn_enc(
    const float* __restrict__ audios, const float* __restrict__ texts,
    const float* __restrict__ videos,
    const float* __restrict__ Wa, const float* __restrict__ ba,
    const float* __restrict__ Wt, const float* __restrict__ bt,
    const float* __restrict__ Wv, const float* __restrict__ bv) {
    const int b   = blockIdx.x;
    const int mod = blockIdx.y;
    const int tid = threadIdx.x;

    const float* x; const float* W; const float* bias; float* out; int K;
    if (mod == 0)      { x = audios; W = Wa; bias = ba; out = g_a1; K = 512; }
    else if (mod == 1) { x = texts;  W = Wt; bias = bt; out = g_t1; K = 1024; }
    else               { x = videos; W = Wv; bias = bv; out = g_v1; K = 512; }

    __shared__ float xs[1024];
    __shared__ float ps[768];

    const float* xb = x + (size_t)b * K;
    for (int i = tid; i < K; i += 768) xs[i] = xb[i];
    __syncthreads();

    const int h  = tid % 96;
    const int g  = tid / 96;           // 0..7
    const int kq = K >> 3;             // 64 or 128
    const int k0 = g * kq;

    float acc = 0.f;
#pragma unroll 8
    for (int k = k0; k < k0 + kq; k++)
        acc += xs[k] * W[k * HDIM + h];
    ps[tid] = acc;
    __syncthreads();

    if (g == 0) {
        float r = bias[h];
#pragma unroll
        for (int i = 0; i < 8; i++) r += ps[h + 96 * i];
        out[b * 97 + 1 + h] = fmaxf(r, 0.f);
        if (h == 0) out[b * 97] = 1.f;
    }
}

// ---------------------------------------------------------------------------
// Kernel 2: main fused trilinear GEMM (y1 partials, pre-bias/relu)
//   152 CTAs x 256 threads, 1 CTA/SM, prefetch distance 3 / 3-stage smem ring
// ---------------------------------------------------------------------------
__global__ void __launch_bounds__(256, 1) tfn_main(const float* __restrict__ W1) {
    extern __shared__ char smx[];
    __half* wb0 = reinterpret_cast<__half*>(smx);
    __half* wb1 = wb0 + WBUFH;
    __half* wb2 = wb1 + WBUFH;
    float*  a1s = reinterpret_cast<float*>(wb2 + WBUFH);
    float*  v1s = a1s + 6208;

    const int tid  = threadIdx.x;
    const int lane = tid & 31;
    const int wid  = tid >> 5;
    const int wm   = wid & 3;    // m-warp: batch rows 16*wm..16*wm+15
    const int wn   = wid >> 2;   // n-warp: cols 48*wn..48*wn+47
    const int gid  = lane >> 2;
    const int tig  = lane & 3;
    const int b0   = wm * 16 + gid;
    const int nbase = wn * 48;

    for (int i = tid; i < 6208; i += 256) { a1s[i] = g_a1[i]; v1s[i] = g_v1[i]; }
    // zero pad rows 97..111 of all three buffers (780 u32 each)
    for (int i = tid; i < 3 * 780; i += 256) {
        int s = i / 780, r = i - s * 780;
        reinterpret_cast<uint32_t*>(wb0 + s * WBUFH + 97 * LDH)[r] = 0;
    }

    // persistent t1 A-fragments as half2 pairs: 7 k16-steps
    __half2 t1f[7][4];
#pragma unroll
    for (int ks = 0; ks < 7; ks++) {
        int ka = ks * 16 + 2 * tig;
        int kb = ka + 8;
        float x0 = (ka     < 97) ? g_t1[b0 * 97 + ka]           : 0.f;
        float x1 = (ka + 1 < 97) ? g_t1[b0 * 97 + ka + 1]       : 0.f;
        float y0 = (ka     < 97) ? g_t1[(b0 + 8) * 97 + ka]     : 0.f;
        float y1 = (ka + 1 < 97) ? g_t1[(b0 + 8) * 97 + ka + 1] : 0.f;
        float x2 = (kb     < 97) ? g_t1[b0 * 97 + kb]           : 0.f;
        float x3 = (kb + 1 < 97) ? g_t1[b0 * 97 + kb + 1]       : 0.f;
        float y2 = (kb     < 97) ? g_t1[(b0 + 8) * 97 + kb]     : 0.f;
        float y3 = (kb + 1 < 97) ? g_t1[(b0 + 8) * 97 + kb + 1] : 0.f;
        t1f[ks][0] = __floats2half2_rn(x0, x1);
        t1f[ks][1] = __floats2half2_rn(y0, y1);
        t1f[ks][2] = __floats2half2_rn(x2, x3);
        t1f[ks][3] = __floats2half2_rn(y2, y3);
    }

    float Y[6][4];
#pragma unroll
    for (int j = 0; j < 6; j++) { Y[j][0] = Y[j][1] = Y[j][2] = Y[j][3] = 0.f; }

    const int bk = blockIdx.x;
    // 9409 = 152*61 + 137 : first 137 blocks take 62 chunks
    const int cstart = (bk < 137) ? bk * 62 : bk * 61 + 137;
    const int ccnt   = (bk < 137) ? 62 : 61;

    const int lrow = lane & 15;          // k row within k16 step
    const int lcol = (lane >> 4) * 8;    // 0 or 8 within n16 block

    auto compute = [&](int av, const __half* curb) {
        const int ca = av / 97;
        const int cv = av - ca * 97;
        const __half2 m0h = __float2half2_rn(a1s[b0 * 97 + ca] * v1s[b0 * 97 + cv]);
        const __half2 m1h = __float2half2_rn(a1s[(b0 + 8) * 97 + ca] * v1s[(b0 + 8) * 97 + cv]);
#pragma unroll
        for (int ks = 0; ks < 7; ks++) {
            const uint32_t A0 = h2u(__hmul2(m0h, t1f[ks][0]));
            const uint32_t A1 = h2u(__hmul2(m1h, t1f[ks][1]));
            const uint32_t A2 = h2u(__hmul2(m0h, t1f[ks][2]));
            const uint32_t A3 = h2u(__hmul2(m1h, t1f[ks][3]));
            const __half* rowp = curb + (ks * 16 + lrow) * LDH + nbase + lcol;
#pragma unroll
            for (int j3 = 0; j3 < 3; j3++) {
                uint32_t saddr =
                    (uint32_t)__cvta_generic_to_shared(rowp + 16 * j3);
                uint32_t B0, B1, B2, B3;
                asm volatile(
                    "ldmatrix.sync.aligned.m8n8.x4.trans.shared.b16 "
                    "{%0,%1,%2,%3}, [%4];"
                    : "=r"(B0), "=r"(B1), "=r"(B2), "=r"(B3) : "r"(saddr));
                mma_f16(Y[2 * j3],     A0, A1, A2, A3, B0, B1);
                mma_f16(Y[2 * j3 + 1], A0, A1, A2, A3, B2, B3);
            }
        }
    };

    // --- prefetch distance 3: 2 reg sets, 3 smem stages ---
    // Invariant at top of iter j (j even): stgB holds chunk j+1, stgA holds
    // chunk j+2. STS(j+1) uses data LDG'd 2 iterations ago -> no stall.
    float4 stgA[10], stgB[10];
    stage_ldg(stgA, W1, cstart, tid);                       // chunk 0
    if (ccnt > 1) stage_ldg(stgB, W1, cstart + 1, tid);     // chunk 1
    stage_sts(wb0, stgA, tid);                              // chunk 0 -> wb0
    if (ccnt > 2) stage_ldg(stgA, W1, cstart + 2, tid);     // chunk 2
    __syncthreads();

    __half *cur = wb0, *nxt = wb1, *spare = wb2;

    for (int ci = 0; ci < ccnt; ci += 2) {
        // even iter: compute chunk ci; stgB holds ci+1
        if (ci + 1 < ccnt) stage_sts(nxt, stgB, tid);
        if (ci + 3 < ccnt) stage_ldg(stgB, W1, cstart + ci + 3, tid);
        compute(cstart + ci, cur);
        __syncthreads();
        { __half* t = cur; cur = nxt; nxt = spare; spare = t; }

        // odd iter: compute chunk ci+1; stgA holds ci+2
        if (ci + 1 < ccnt) {
            if (ci + 2 < ccnt) stage_sts(nxt, stgA, tid);
            if (ci + 4 < ccnt) stage_ldg(stgA, W1, cstart + ci + 4, tid);
            compute(cstart + ci + 1, cur);
            __syncthreads();
            { __half* t = cur; cur = nxt; nxt = spare; spare = t; }
        }
    }

    // write fp32 partials [bk][b][h]
    float* dst = g_part + (size_t)bk * (BDIM * HDIM);
#pragma unroll
    for (int j = 0; j < 6; j++) {
        int h = nbase + 8 * j + 2 * tig;
        *reinterpret_cast<float2*>(dst + b0 * HDIM + h) =
            make_float2(Y[j][0], Y[j][1]);
        *reinterpret_cast<float2*>(dst + (b0 + 8) * HDIM + h) =
            make_float2(Y[j][2], Y[j][3]);
    }
}

// ---------------------------------------------------------------------------
// Kernel 3: reduce partials + bias/relu + W2 + heads. One block per batch row.
// ---------------------------------------------------------------------------
__global__ void __launch_bounds__(768) tfn_tail(
    const float* __restrict__ b1, const float* __restrict__ W2,
    const float* __restrict__ b2,
    const float* __restrict__ Wo1, const float* __restrict__ bo1,
    const float* __restrict__ Wo2, const float* __restrict__ bo2,
    const float* __restrict__ Wo3, const float* __restrict__ bo3,
    float* __restrict__ out) {
    __shared__ float ps[768];
    __shared__ float yr[HDIM];
    __shared__ float fs[HDIM];
    const int b   = blockIdx.x;
    const int tid = threadIdx.x;
    const int h   = tid % 96;
    const int g   = tid / 96;   // 0..7

    float acc = 0.f;
#pragma unroll 4
    for (int p = g; p < NBLK; p += 8)
        acc += g_part[(size_t)p * (BDIM * HDIM) + b * HDIM + h];
    ps[tid] = acc;
    __syncthreads();

    if (g == 0) {
        float r = b1[h];
#pragma unroll
        for (int i = 0; i < 8; i++) r += ps[h + 96 * i];
        yr[h] = fmaxf(r, 0.f);
    }
    __syncthreads();

    if (g == 0) {
        float f = b2[h];
#pragma unroll 8
        for (int k = 0; k < HDIM; k++) f += yr[k] * W2[k * HDIM + h];
        f = fmaxf(f, 0.f);
        fs[h] = f;
        out[b * HDIM + h] = f;
    }
    __syncthreads();

    if (tid < 6) {
        float a = bo1[tid];
        for (int k = 0; k < HDIM; k++) a += fs[k] * Wo1[k * 6 + tid];
        out[6144 + b * 6 + tid] = a;
    } else if (tid == 6) {
        float a = bo2[0];
        for (int k = 0; k < HDIM; k++) a += fs[k] * Wo2[k];
        out[6528 + b] = a;
    } else if (tid < 10) {
        int o = tid - 7;
        float a = bo3[o];
        for (int k = 0; k < HDIM; k++) a += fs[k] * Wo3[k * 3 + o];
        out[6592 + b * 3 + o] = a;
    }
    if (b == 0 && tid == 95) out[6784] = 0.f;  // interloss
}

// ---------------------------------------------------------------------------

extern "C" void kernel_launch(void* const* d_in, const int* in_sizes, int n_in,
                              void* d_out, int out_size) {
    (void)in_sizes; (void)n_in; (void)out_size;
    const float* audios = (const float*)d_in[0];
    const float* texts  = (const float*)d_in[1];
    const float* videos = (const float*)d_in[2];
    const float* Wa  = (const float*)d_in[3];
    const float* ba  = (const float*)d_in[4];
    const float* Wt  = (const float*)d_in[5];
    const float* bt  = (const float*)d_in[6];
    const float* Wv  = (const float*)d_in[7];
    const float* bv  = (const float*)d_in[8];
    const float* W1  = (const float*)d_in[9];
    const float* b1  = (const float*)d_in[10];
    const float* W2  = (const float*)d_in[11];
    const float* b2  = (const float*)d_in[12];
    const float* Wo1 = (const float*)d_in[13];
    const float* bo1 = (const float*)d_in[14];
    const float* Wo2 = (const float*)d_in[15];
    const float* bo2 = (const float*)d_in[16];
    const float* Wo3 = (const float*)d_in[17];
    const float* bo3 = (const float*)d_in[18];
    float* out = (float*)d_out;

    cudaFuncSetAttribute(tfn_main, cudaFuncAttributeMaxDynamicSharedMemorySize,
                         SMEM_BYTES);

    tfn_enc<<<dim3(64, 3), 768>>>(audios, texts, videos, Wa, ba, Wt, bt, Wv, bv);
    tfn_main<<<NBLK, 256, SMEM_BYTES>>>(W1);
    tfn_tail<<<64, 768>>>(b1, W2, b2, Wo1, bo1, Wo2, bo2, Wo3, bo3, out);
}